// round 4
// baseline (speedup 1.0000x reference)
#include <cuda_runtime.h>

#define T_STEPS 784
#define HDIM    110
#define G4      440
#define NTH     480
#define NCLS    10

// ---------- f32x2 packed helpers ----------
__device__ __forceinline__ unsigned long long pk2(float x, float y) {
    unsigned long long r;
    asm("mov.b64 %0, {%1,%2};" : "=l"(r) : "f"(x), "f"(y));
    return r;
}
__device__ __forceinline__ float2 upk2(unsigned long long a) {
    float2 r;
    asm("mov.b64 {%0,%1}, %2;" : "=f"(r.x), "=f"(r.y) : "l"(a));
    return r;
}
__device__ __forceinline__ void ff2(unsigned long long& acc,
                                    unsigned long long a,
                                    unsigned long long b) {
    asm("fma.rn.f32x2 %0, %1, %2, %0;" : "+l"(acc) : "l"(a), "l"(b));
}

// ---------- fast transcendentals (MUFU-based) ----------
__device__ __forceinline__ float sigm(float x) {
    return __fdividef(1.0f, 1.0f + __expf(-x));   // x<<0: rcp(inf)=0 ✓
}
__device__ __forceinline__ float tanh_(float x) {
    float e = __expf(2.0f * x);                   // inf-safe at both ends ✓
    return 1.0f - __fdividef(2.0f, e + 1.0f);
}

__global__ void zero_slot_kernel(float* o, int idx) { o[idx] = 0.0f; }

__global__ void __launch_bounds__(NTH, 1) skiplstm_kernel(
    const float* __restrict__ x,      // [B, T, 1]
    const float* __restrict__ Wih,    // [440, 1]
    const float* __restrict__ Whh,    // [440, 110]
    const float* __restrict__ bg,     // [440]
    const float* __restrict__ Wp,     // [1, 110]
    const float* __restrict__ bp_,    // [1]
    const float* __restrict__ h0,     // [110]
    const float* __restrict__ c0,     // [110]
    const float* __restrict__ Wfc,    // [10, 110]
    const float* __restrict__ bfc,    // [10]
    float* __restrict__ out,          // [B*10 + 1]
    int last_idx)
{
    __shared__ float sx[2][T_STEPS];                 // per-batch x sequence
    __shared__ __align__(16) float smh[2][112];      // h state
    __shared__ float smc[2][HDIM];                   // c state (== c_new)
    __shared__ float smg[2][G4];                     // gate pre-activations
    __shared__ float swp[112];                       // W_p
    __shared__ float swih[G4];                       // W_ih column
    __shared__ float sbj[G4];                        // gate bias
    __shared__ float sflags[2];                      // activity flags (this step)

    const int tid = threadIdx.x;
    const int b0g = blockIdx.x * 2;

    for (int i = tid; i < T_STEPS; i += NTH) {
        sx[0][i] = x[b0g * T_STEPS + i];
        sx[1][i] = x[(b0g + 1) * T_STEPS + i];
    }
    for (int i = tid; i < 112; i += NTH) {
        float hv = (i < HDIM) ? h0[i] : 0.0f;
        smh[0][i] = hv;
        smh[1][i] = hv;
        swp[i] = (i < HDIM) ? Wp[i] : 0.0f;
        if (i < HDIM) {
            float cv = c0[i];
            smc[0][i] = cv;
            smc[1][i] = cv;
        }
    }
    if (tid < G4) {
        swih[tid] = Wih[tid];
        sbj[tid]  = bg[tid];
    }

    // ---- my gate row of W_hh: 55 packed f32x2 = 110 regs (warps 0-13) ----
    unsigned long long w[55];
    const bool gv = (tid < G4);
    {
        const float* wr = Whh + (gv ? tid : 0) * HDIM;
#pragma unroll
        for (int k = 0; k < 55; k++)
            w[k] = gv ? pk2(wr[2 * k], wr[2 * k + 1]) : 0ull;
    }
    const float bp = bp_[0];
    __syncthreads();

    const ulonglong2* __restrict__ hq0 = (const ulonglong2*)smh[0];
    const ulonglong2* __restrict__ hq1 = (const ulonglong2*)smh[1];
    const unsigned long long* __restrict__ h64_0 = (const unsigned long long*)smh[0];
    const unsigned long long* __restrict__ h64_1 = (const unsigned long long*)smh[1];

    // warp-14-only recurrence state (also present harmlessly elsewhere)
    float u0 = 1.0f, u1 = 1.0f;
    bool  a0 = true, a1 = true;
    int   totu = 0;

    for (int t = 0; t < T_STEPS; t++) {
        if (tid < G4 + 8) {
            // ======== GEMV phase: both lanes, UNCONDITIONAL ========
            {
                unsigned long long ax = 0ull, ay = 0ull;
#pragma unroll
                for (int k = 0; k < 27; k++) {
                    ulonglong2 hv = hq0[k];
                    ff2(ax, w[2 * k],     hv.x);
                    ff2(ay, w[2 * k + 1], hv.y);
                }
                ff2(ax, w[54], h64_0[54]);
                if (gv) {
                    float2 vx = upk2(ax), vy = upk2(ay);
                    smg[0][tid] = (vx.x + vx.y) + (vy.x + vy.y)
                                + fmaf(sx[0][t], swih[tid], sbj[tid]);
                }
            }
            {
                unsigned long long ax = 0ull, ay = 0ull;
#pragma unroll
                for (int k = 0; k < 27; k++) {
                    ulonglong2 hv = hq1[k];
                    ff2(ax, w[2 * k],     hv.x);
                    ff2(ay, w[2 * k + 1], hv.y);
                }
                ff2(ax, w[54], h64_1[54]);
                if (gv) {
                    float2 vx = upk2(ax), vy = upk2(ay);
                    smg[1][tid] = (vx.x + vx.y) + (vy.x + vy.y)
                                + fmaf(sx[1][t], swih[tid], sbj[tid]);
                }
            }
        } else {
            // ======== warp 14: du / u / activity (overlaps GEMV) ========
            // smc currently holds c_{t-1}; du_{t-1} = sigm(Wp·c_{t-1} + bp).
            // If a lane was skipped, smc unchanged -> recomputed du == carried du. ✓
            if (t > 0) {
                const int lane = tid & 31;
                const int half = lane >> 4;          // 0: batch lane0, 1: lane1
                const int l16  = lane & 15;
                float p = 0.0f;
                for (int d = l16; d < HDIM; d += 16)
                    p += smc[half][d] * swp[d];
#pragma unroll
                for (int off = 8; off; off >>= 1)
                    p += __shfl_xor_sync(0xffffffffu, p, off);
                float q = __shfl_xor_sync(0xffffffffu, p, 16);
                float dot0 = half ? q : p;
                float dot1 = half ? p : q;
                float du0 = sigm(dot0 + bp);
                float du1 = sigm(dot1 + bp);
                u0 = a0 ? du0 : u0 + fminf(du0, 1.0f - u0);
                u1 = a1 ? du1 : u1 + fminf(du1, 1.0f - u1);
                a0 = (rintf(u0) != 0.0f);
                a1 = (rintf(u1) != 0.0f);
            }
            totu += (a0 ? 1 : 0) + (a1 ? 1 : 0);
            if ((tid & 31) == 0) {
                sflags[0] = a0 ? 1.0f : 0.0f;
                sflags[1] = a1 ? 1.0f : 0.0f;
            }
        }
        __syncthreads();

        // ======== pointwise phase (warps 0-7), gated per batch lane ========
        if (tid < 256) {
            const int b = tid >> 7;
            const int d = tid & 127;
            if (sflags[b] != 0.0f && d < HDIM) {
                float i_ = sigm (smg[b][d]);
                float f_ = sigm (smg[b][HDIM + d]);
                float g_ = tanh_(smg[b][2 * HDIM + d]);
                float o_ = sigm (smg[b][3 * HDIM + d]);
                float cn = f_ * smc[b][d] + i_ * g_;
                smc[b][d] = cn;
                smh[b][d] = o_ * tanh_(cn);
            }
        }
        __syncthreads();
    }

    // ---- FC head ----
    const int wid = tid >> 5, lane = tid & 31;
    for (int p = wid; p < 2 * NCLS; p += NTH / 32) {
        const int b = p / NCLS, cls = p % NCLS;
        const float* wf = Wfc + cls * HDIM;
        float s = 0.0f;
        for (int d = lane; d < HDIM; d += 32) s += smh[b][d] * wf[d];
#pragma unroll
        for (int off = 16; off; off >>= 1)
            s += __shfl_xor_sync(0xffffffffu, s, off);
        if (lane == 0) out[(b0g + b) * NCLS + cls] = s + bfc[cls];
    }

    // total_u from warp 14's lane 0 (exact integer-valued float adds)
    if (tid == G4 + 8) atomicAdd(&out[last_idx], (float)totu);
}

extern "C" void kernel_launch(void* const* d_in, const int* in_sizes, int n_in,
                              void* d_out, int out_size) {
    const float* x    = (const float*)d_in[0];
    const float* Wih  = (const float*)d_in[1];
    const float* Whh  = (const float*)d_in[2];
    const float* bg   = (const float*)d_in[3];
    const float* Wp   = (const float*)d_in[4];
    const float* bp   = (const float*)d_in[5];
    const float* h0   = (const float*)d_in[6];
    const float* c0   = (const float*)d_in[7];
    const float* Wfc  = (const float*)d_in[8];
    const float* bfc  = (const float*)d_in[9];
    float* out = (float*)d_out;

    const int B = in_sizes[0] / T_STEPS;   // I = 1
    const int last = out_size - 1;

    zero_slot_kernel<<<1, 1>>>(out, last);
    skiplstm_kernel<<<B / 2, NTH>>>(x, Wih, Whh, bg, Wp, bp, h0, c0,
                                    Wfc, bfc, out, last);
}

// round 5
// speedup vs baseline: 1.2755x; 1.2755x over previous
#include <cuda_runtime.h>

#define T_STEPS 784
#define HDIM    110
#define G4      440
#define NTH     480
#define NCLS    10

// ---------- f32x2 packed helpers ----------
__device__ __forceinline__ unsigned long long pk2(float x, float y) {
    unsigned long long r;
    asm("mov.b64 %0, {%1,%2};" : "=l"(r) : "f"(x), "f"(y));
    return r;
}
__device__ __forceinline__ float2 upk2(unsigned long long a) {
    float2 r;
    asm("mov.b64 {%0,%1}, %2;" : "=f"(r.x), "=f"(r.y) : "l"(a));
    return r;
}
__device__ __forceinline__ void ff2(unsigned long long& acc,
                                    unsigned long long a,
                                    unsigned long long b) {
    asm("fma.rn.f32x2 %0, %1, %2, %0;" : "+l"(acc) : "l"(a), "l"(b));
}

// ---------- activations ----------
__device__ __forceinline__ float tanha(float x) {          // MUFU.TANH
    float r;
    asm("tanh.approx.f32 %0, %1;" : "=f"(r) : "f"(x));
    return r;
}
__device__ __forceinline__ float sigmf(float x) {          // fast gate sigmoid
    return fmaf(0.5f, tanha(0.5f * x), 0.5f);
}
__device__ __forceinline__ float sigm_precise(float x) {   // du decision path
    return __fdividef(1.0f, 1.0f + __expf(-x));
}

__global__ void zero_slot_kernel(float* o, int idx) { o[idx] = 0.0f; }

__global__ void __launch_bounds__(NTH, 1) skiplstm_kernel(
    const float* __restrict__ x,      // [B, T, 1]
    const float* __restrict__ Wih,    // [440, 1]
    const float* __restrict__ Whh,    // [440, 110]
    const float* __restrict__ bg,     // [440]
    const float* __restrict__ Wp,     // [1, 110]
    const float* __restrict__ bp_,    // [1]
    const float* __restrict__ h0,     // [110]
    const float* __restrict__ c0,     // [110]
    const float* __restrict__ Wfc,    // [10, 110]
    const float* __restrict__ bfc,    // [10]
    float* __restrict__ out,          // [B*10 + 1]
    int last_idx)
{
    __shared__ float sx[2][T_STEPS];                 // per-batch x sequence
    __shared__ __align__(16) float smh[2][112];      // h state (padded; [110],[111]=0)
    __shared__ float smc[2][HDIM];                   // c state
    __shared__ float smg[2][G4];                     // gate pre-activations
    __shared__ float swp[112];                       // W_p
    __shared__ float swih[G4];                       // W_ih column
    __shared__ float sbj[G4];                        // gate bias
    __shared__ float sflags[2];                      // activity flags

    const int tid = threadIdx.x;
    const int b0g = blockIdx.x * 2;

    for (int i = tid; i < T_STEPS; i += NTH) {
        sx[0][i] = x[b0g * T_STEPS + i];
        sx[1][i] = x[(b0g + 1) * T_STEPS + i];
    }
    for (int i = tid; i < 112; i += NTH) {
        float hv = (i < HDIM) ? h0[i] : 0.0f;
        smh[0][i] = hv;
        smh[1][i] = hv;
        swp[i] = (i < HDIM) ? Wp[i] : 0.0f;
        if (i < HDIM) {
            float cv = c0[i];
            smc[0][i] = cv;
            smc[1][i] = cv;
        }
    }
    if (tid < G4) {
        swih[tid] = Wih[tid];
        sbj[tid]  = bg[tid];
    }

    // ---- my gate row of W_hh: 55 packed f32x2 = 110 regs (warps 0-13) ----
    unsigned long long w[55];
    const bool gv = (tid < G4);
    {
        const float* wr = Whh + (gv ? tid : 0) * HDIM;
#pragma unroll
        for (int k = 0; k < 55; k++)
            w[k] = gv ? pk2(wr[2 * k], wr[2 * k + 1]) : 0ull;
    }
    const float bp = bp_[0];
    __syncthreads();

    const ulonglong2* __restrict__ hq0 = (const ulonglong2*)smh[0];
    const ulonglong2* __restrict__ hq1 = (const ulonglong2*)smh[1];
    const unsigned long long* __restrict__ h64_0 = (const unsigned long long*)smh[0];
    const unsigned long long* __restrict__ h64_1 = (const unsigned long long*)smh[1];

    // warp-14 recurrence state
    float u0 = 1.0f, u1 = 1.0f;
    bool  a0 = true, a1 = true;
    int   totu = 0;

    for (int t = 0; t < T_STEPS; t++) {
        if (tid < G4 + 8) {
            // ======== GEMV phase: both lanes INTERLEAVED per k ========
            unsigned long long ax0 = 0ull, ay0 = 0ull;
            unsigned long long ax1 = 0ull, ay1 = 0ull;
#pragma unroll
            for (int k = 0; k < 27; k++) {
                ulonglong2 c0v = hq0[k];           // loads issued back-to-back;
                ulonglong2 c1v = hq1[k];           // consumers 2-4 instr later
                ff2(ax0, w[2 * k],     c0v.x);
                ff2(ay0, w[2 * k + 1], c0v.y);
                ff2(ax1, w[2 * k],     c1v.x);
                ff2(ay1, w[2 * k + 1], c1v.y);
            }
            {   // tail: floats 108,109
                unsigned long long t0 = h64_0[54];
                unsigned long long t1 = h64_1[54];
                ff2(ax0, w[54], t0);
                ff2(ax1, w[54], t1);
            }
            if (gv) {
                float2 vx0 = upk2(ax0), vy0 = upk2(ay0);
                float2 vx1 = upk2(ax1), vy1 = upk2(ay1);
                float xb0 = fmaf(sx[0][t], swih[tid], sbj[tid]);
                float xb1 = fmaf(sx[1][t], swih[tid], sbj[tid]);
                smg[0][tid] = (vx0.x + vx0.y) + (vy0.x + vy0.y) + xb0;
                smg[1][tid] = (vx1.x + vx1.y) + (vy1.x + vy1.y) + xb1;
            }
        } else {
            // ======== warp 14: du / u / activity (overlaps GEMV) ========
            if (t > 0) {
                const int lane = tid & 31;
                const int half = lane >> 4;
                const int l16  = lane & 15;
                float p = 0.0f;
                for (int d = l16; d < HDIM; d += 16)
                    p += smc[half][d] * swp[d];
#pragma unroll
                for (int off = 8; off; off >>= 1)
                    p += __shfl_xor_sync(0xffffffffu, p, off);
                float q = __shfl_xor_sync(0xffffffffu, p, 16);
                float dot0 = half ? q : p;
                float dot1 = half ? p : q;
                float du0 = sigm_precise(dot0 + bp);
                float du1 = sigm_precise(dot1 + bp);
                u0 = a0 ? du0 : u0 + fminf(du0, 1.0f - u0);
                u1 = a1 ? du1 : u1 + fminf(du1, 1.0f - u1);
                a0 = (rintf(u0) != 0.0f);
                a1 = (rintf(u1) != 0.0f);
            }
            totu += (a0 ? 1 : 0) + (a1 ? 1 : 0);
            if ((tid & 31) == 0) {
                sflags[0] = a0 ? 1.0f : 0.0f;
                sflags[1] = a1 ? 1.0f : 0.0f;
            }
        }
        __syncthreads();

        // ======== pointwise phase (warps 0-7), gated per batch lane ========
        if (tid < 256) {
            const int b = tid >> 7;
            const int d = tid & 127;
            if (sflags[b] != 0.0f && d < HDIM) {
                float i_ = sigmf(smg[b][d]);
                float f_ = sigmf(smg[b][HDIM + d]);
                float g_ = tanha(smg[b][2 * HDIM + d]);
                float o_ = sigmf(smg[b][3 * HDIM + d]);
                float cn = f_ * smc[b][d] + i_ * g_;
                smc[b][d] = cn;
                smh[b][d] = o_ * tanha(cn);
            }
        }
        __syncthreads();
    }

    // ---- FC head ----
    const int wid = tid >> 5, lane = tid & 31;
    for (int p = wid; p < 2 * NCLS; p += NTH / 32) {
        const int b = p / NCLS, cls = p % NCLS;
        const float* wf = Wfc + cls * HDIM;
        float s = 0.0f;
        for (int d = lane; d < HDIM; d += 32) s += smh[b][d] * wf[d];
#pragma unroll
        for (int off = 16; off; off >>= 1)
            s += __shfl_xor_sync(0xffffffffu, s, off);
        if (lane == 0) out[(b0g + b) * NCLS + cls] = s + bfc[cls];
    }

    if (tid == G4 + 8) atomicAdd(&out[last_idx], (float)totu);
}

extern "C" void kernel_launch(void* const* d_in, const int* in_sizes, int n_in,
                              void* d_out, int out_size) {
    const float* x    = (const float*)d_in[0];
    const float* Wih  = (const float*)d_in[1];
    const float* Whh  = (const float*)d_in[2];
    const float* bg   = (const float*)d_in[3];
    const float* Wp   = (const float*)d_in[4];
    const float* bp   = (const float*)d_in[5];
    const float* h0   = (const float*)d_in[6];
    const float* c0   = (const float*)d_in[7];
    const float* Wfc  = (const float*)d_in[8];
    const float* bfc  = (const float*)d_in[9];
    float* out = (float*)d_out;

    const int B = in_sizes[0] / T_STEPS;   // I = 1
    const int last = out_size - 1;

    zero_slot_kernel<<<1, 1>>>(out, last);
    skiplstm_kernel<<<B / 2, NTH>>>(x, Wih, Whh, bg, Wp, bp, h0, c0,
                                    Wfc, bfc, out, last);
}